// round 1
// baseline (speedup 1.0000x reference)
#include <cuda_runtime.h>
#include <math.h>

#define NBATCH 8
#define TSEQ   2048
#define CDIM   128

// -------- scratch (static __device__ per harness rules) --------
__device__ float g_Q [(size_t)NBATCH * TSEQ * CDIM];
__device__ float g_K [(size_t)NBATCH * TSEQ * CDIM];
__device__ float g_S [(size_t)NBATCH * TSEQ * TSEQ];   // scores scratch (134 MB)
__device__ float g_OA[(size_t)NBATCH * TSEQ * CDIM];   // attention @ V

// ============================================================================
// Generic C[m, n] = scale * sum_c A[m,c] * B[n,c]  (+ bias[n])
// Inner dim fixed at 128 (contiguous). Tiles 128x128, 256 threads, 8x8/thread.
// Smem tiles stored transposed ([c][r], stride 128) — conflict-free stores
// (lane-consecutive rows) and conflict-free reads (split 4+4 fragments).
// ============================================================================
__global__ __launch_bounds__(256) void gemm_abT(
    const float* __restrict__ A, const float* __restrict__ B,
    const float* __restrict__ bias, float* __restrict__ Cc,
    long long sA, long long sB, long long sC,
    int ldc, int tilesPerBlock, float scale)
{
    extern __shared__ float sm[];
    float* As = sm;              // [128][128] transposed
    float* Bs = sm + 128 * 128;  // [128][128] transposed

    const int tid = threadIdx.x;
    const int tx = tid & 15;
    const int ty = tid >> 4;
    const int bz = blockIdx.z;

    A  += sA * bz;
    B  += sB * bz;
    Cc += sC * bz;

    const int m0 = blockIdx.y * 128;

    // ---- load A tile (rows m0..m0+127), transposed into smem ----
    {
        const float4* src = (const float4*)(A + (size_t)m0 * 128);
        #pragma unroll
        for (int i = tid; i < 128 * 32; i += 256) {
            int r = i & 127, cq = i >> 7;
            float4 v = src[(size_t)r * 32 + cq];
            float* d = As + (cq * 4) * 128 + r;
            d[0] = v.x; d[128] = v.y; d[256] = v.z; d[384] = v.w;
        }
    }

    for (int t = 0; t < tilesPerBlock; t++) {
        const int n0 = (blockIdx.x * tilesPerBlock + t) * 128;

        __syncthreads();  // protect Bs from previous iteration readers (and As 1st iter)
        {
            const float4* src = (const float4*)(B + (size_t)n0 * 128);
            #pragma unroll
            for (int i = tid; i < 128 * 32; i += 256) {
                int r = i & 127, cq = i >> 7;
                float4 v = src[(size_t)r * 32 + cq];
                float* d = Bs + (cq * 4) * 128 + r;
                d[0] = v.x; d[128] = v.y; d[256] = v.z; d[384] = v.w;
            }
        }
        __syncthreads();

        float acc[8][8];
        #pragma unroll
        for (int i = 0; i < 8; i++)
            #pragma unroll
            for (int j = 0; j < 8; j++) acc[i][j] = 0.f;

        #pragma unroll 4
        for (int c = 0; c < 128; c++) {
            const float* ac = As + c * 128;
            const float* bc = Bs + c * 128;
            float4 a0 = *(const float4*)(ac + ty * 4);
            float4 a1 = *(const float4*)(ac + 64 + ty * 4);
            float4 b0 = *(const float4*)(bc + tx * 4);
            float4 b1 = *(const float4*)(bc + 64 + tx * 4);
            float a[8] = {a0.x, a0.y, a0.z, a0.w, a1.x, a1.y, a1.z, a1.w};
            float b[8] = {b0.x, b0.y, b0.z, b0.w, b1.x, b1.y, b1.z, b1.w};
            #pragma unroll
            for (int i = 0; i < 8; i++)
                #pragma unroll
                for (int j = 0; j < 8; j++)
                    acc[i][j] += a[i] * b[j];
        }

        // ---- store ----
        #pragma unroll
        for (int ih = 0; ih < 2; ih++) {
            #pragma unroll
            for (int i = 0; i < 4; i++) {
                const int row = m0 + ih * 64 + ty * 4 + i;
                #pragma unroll
                for (int jh = 0; jh < 2; jh++) {
                    const int col = n0 + jh * 64 + tx * 4;
                    float4 o;
                    o.x = acc[ih * 4 + i][jh * 4 + 0] * scale;
                    o.y = acc[ih * 4 + i][jh * 4 + 1] * scale;
                    o.z = acc[ih * 4 + i][jh * 4 + 2] * scale;
                    o.w = acc[ih * 4 + i][jh * 4 + 3] * scale;
                    if (bias) {
                        float4 bb = *(const float4*)(bias + col);
                        o.x += bb.x; o.y += bb.y; o.z += bb.z; o.w += bb.w;
                    }
                    *(float4*)(Cc + (size_t)row * ldc + col) = o;
                }
            }
        }
    }
}

// ============================================================================
// One warp per (n, q) row: top-3 over 2048 scores, softmax of 3, write the
// (mostly zero) attention row, and gather the weighted sum of 3 value rows.
// ============================================================================
#define INS(vv, cc) do { float _v = (vv); int _c = (cc);                     \
    if (_v > v2) {                                                           \
        if (_v > v1) {                                                       \
            if (_v > v0) { v2 = v1; i2 = i1; v1 = v0; i1 = i0; v0 = _v; i0 = _c; } \
            else         { v2 = v1; i2 = i1; v1 = _v; i1 = _c; }             \
        } else           { v2 = _v; i2 = _c; }                               \
    } } while (0)

__global__ __launch_bounds__(256) void topk_attn(
    const float* __restrict__ S, const float* __restrict__ E,
    float* __restrict__ attn, float* __restrict__ oattn)
{
    const int gw   = (blockIdx.x * 256 + threadIdx.x) >> 5;  // 0..16383 = n*2048+q
    const int lane = threadIdx.x & 31;

    const float4* r4 = (const float4*)(S + (size_t)gw * TSEQ);

    float v0 = -INFINITY, v1 = -INFINITY, v2 = -INFINITY;
    int   i0 = 0, i1 = 0, i2 = 0;

    #pragma unroll
    for (int f = 0; f < 16; f++) {
        float4 x = r4[f * 32 + lane];
        int c = f * 128 + lane * 4;
        INS(x.x, c); INS(x.y, c + 1); INS(x.z, c + 2); INS(x.w, c + 3);
    }

    // reduce to lane 0 (disjoint lane sets -> no duplicates)
    #pragma unroll
    for (int off = 16; off; off >>= 1) {
        float ov0 = __shfl_down_sync(0xffffffffu, v0, off);
        float ov1 = __shfl_down_sync(0xffffffffu, v1, off);
        float ov2 = __shfl_down_sync(0xffffffffu, v2, off);
        int   oi0 = __shfl_down_sync(0xffffffffu, i0, off);
        int   oi1 = __shfl_down_sync(0xffffffffu, i1, off);
        int   oi2 = __shfl_down_sync(0xffffffffu, i2, off);
        INS(ov0, oi0); INS(ov1, oi1); INS(ov2, oi2);
    }
    v0 = __shfl_sync(0xffffffffu, v0, 0);
    v1 = __shfl_sync(0xffffffffu, v1, 0);
    v2 = __shfl_sync(0xffffffffu, v2, 0);
    i0 = __shfl_sync(0xffffffffu, i0, 0);
    i1 = __shfl_sync(0xffffffffu, i1, 0);
    i2 = __shfl_sync(0xffffffffu, i2, 0);

    const float e1 = expf(v1 - v0);
    const float e2 = expf(v2 - v0);
    const float inv = 1.f / (1.f + e1 + e2);
    const float w0 = inv, w1 = e1 * inv, w2 = e2 * inv;

    // write attention row: zeros + 3 weights (race-free: owner-lane selects)
    float4* a4 = (float4*)(attn + (size_t)gw * TSEQ);
    #pragma unroll
    for (int f = 0; f < 16; f++) {
        const int c = f * 128 + lane * 4;
        float4 z;
        z.x = (i0 == c    ) ? w0 : (i1 == c    ) ? w1 : (i2 == c    ) ? w2 : 0.f;
        z.y = (i0 == c + 1) ? w0 : (i1 == c + 1) ? w1 : (i2 == c + 1) ? w2 : 0.f;
        z.z = (i0 == c + 2) ? w0 : (i1 == c + 2) ? w1 : (i2 == c + 2) ? w2 : 0.f;
        z.w = (i0 == c + 3) ? w0 : (i1 == c + 3) ? w1 : (i2 == c + 3) ? w2 : 0.f;
        a4[f * 32 + lane] = z;
    }

    // oattn = w0*V[i0] + w1*V[i1] + w2*V[i2]   (V = raw embeddings)
    const int n = gw >> 11;
    const float4* V0 = (const float4*)(E + ((size_t)(n * TSEQ + i0)) * CDIM);
    const float4* V1 = (const float4*)(E + ((size_t)(n * TSEQ + i1)) * CDIM);
    const float4* V2 = (const float4*)(E + ((size_t)(n * TSEQ + i2)) * CDIM);
    float4 p0 = V0[lane], p1 = V1[lane], p2 = V2[lane];
    float4 o;
    o.x = w0 * p0.x + w1 * p1.x + w2 * p2.x;
    o.y = w0 * p0.y + w1 * p1.y + w2 * p2.y;
    o.z = w0 * p0.z + w1 * p1.z + w2 * p2.z;
    o.w = w0 * p0.w + w1 * p1.w + w2 * p2.w;
    *(float4*)(oattn + (size_t)gw * CDIM + lane * 4) = o;
}

// ============================================================================
extern "C" void kernel_launch(void* const* d_in, const int* in_sizes, int n_in,
                              void* d_out, int out_size)
{
    const float* E  = (const float*)d_in[0];
    // d_in[1] = ac (unused by forward)
    const float* Wq = (const float*)d_in[2];
    const float* Wk = (const float*)d_in[3];
    const float* Wo = (const float*)d_in[4];
    const float* bo = (const float*)d_in[5];

    float* out  = (float*)d_out;                                 // [8,2048,128]
    float* attn = out + (size_t)NBATCH * TSEQ * CDIM;            // [8,1,2048,2048]

    float *pQ, *pK, *pS, *pOA;
    cudaGetSymbolAddress((void**)&pQ,  g_Q);
    cudaGetSymbolAddress((void**)&pK,  g_K);
    cudaGetSymbolAddress((void**)&pS,  g_S);
    cudaGetSymbolAddress((void**)&pOA, g_OA);

    const int SMEM = 128 * 128 * 2 * sizeof(float);  // 131072
    cudaFuncSetAttribute(gemm_abT, cudaFuncAttributeMaxDynamicSharedMemorySize, SMEM);

    const float scl = 0.08838834764831845f;  // 1/sqrt(128)
    dim3 blk(256);

    // Q = E @ Wq^T, K = E @ Wk^T   (16384 x 128)
    gemm_abT<<<dim3(1, 128, 1), blk, SMEM>>>(E, Wq, nullptr, pQ, 0, 0, 0, 128, 1, 1.f);
    gemm_abT<<<dim3(1, 128, 1), blk, SMEM>>>(E, Wk, nullptr, pK, 0, 0, 0, 128, 1, 1.f);

    // S[n] = Q[n] @ K[n]^T / sqrt(128)   (per batch 2048 x 2048)
    gemm_abT<<<dim3(4, 16, NBATCH), blk, SMEM>>>(
        pQ, pK, nullptr, pS,
        (long long)TSEQ * CDIM, (long long)TSEQ * CDIM, (long long)TSEQ * TSEQ,
        TSEQ, 4, scl);

    // top-3 + softmax + attention write + A@V
    topk_attn<<<2048, 256>>>(pS, E, attn, pOA);

    // out = OA @ Wo^T + bo
    gemm_abT<<<dim3(1, 128, 1), blk, SMEM>>>(pOA, Wo, bo, out, 0, 0, 0, 128, 1, 1.f);
}

// round 3
// speedup vs baseline: 2.2812x; 2.2812x over previous
#include <cuda_runtime.h>
#include <cuda_bf16.h>
#include <math.h>
#include <stdint.h>

#define NBATCH 8
#define TSEQ   2048
#define CDIM   128
#define SCL    0.08838834764831845f   // 1/sqrt(128)

// -------- scratch (static __device__ per harness rules) --------
__device__ float         g_Qf[(size_t)NBATCH * TSEQ * CDIM];   // fp32 Q (raw)
__device__ float         g_Kf[(size_t)NBATCH * TSEQ * CDIM];   // fp32 K (raw)
__device__ __nv_bfloat16 g_Qb[(size_t)NBATCH * TSEQ * CDIM];   // bf16 Q (pre-scaled)
__device__ __nv_bfloat16 g_Kb[(size_t)NBATCH * TSEQ * CDIM];   // bf16 K
__device__ float         g_S [(size_t)NBATCH * TSEQ * TSEQ];   // approx scores
__device__ float         g_OA[(size_t)NBATCH * TSEQ * CDIM];   // attention @ V

__device__ __forceinline__ uint32_t s2u(const void* p) {
    uint32_t a;
    asm("{ .reg .u64 t; cvta.to.shared.u64 t, %1; cvt.u32.u64 %0, t; }" : "=r"(a) : "l"(p));
    return a;
}

// ============================================================================
// Q/K projection (SIMT fp32): writes fp32 (raw) and bf16 (Q scaled by 1/sqrt128)
// ============================================================================
__global__ __launch_bounds__(256) void proj_split(
    const float* __restrict__ E, const float* __restrict__ Wq, const float* __restrict__ Wk)
{
    extern __shared__ float smf[];
    float* As = smf;
    float* Bs = smf + 128 * 128;
    const int tid = threadIdx.x, tx = tid & 15, ty = tid >> 4;
    const int m0 = blockIdx.x * 128;
    const int isK = blockIdx.y;
    const float* W = isK ? Wk : Wq;
    float*         df = isK ? g_Kf : g_Qf;
    __nv_bfloat16* db = isK ? g_Kb : g_Qb;
    const float bscale = isK ? 1.f : SCL;

    {
        const float4* src = (const float4*)(E + (size_t)m0 * 128);
        #pragma unroll
        for (int i = tid; i < 128 * 32; i += 256) {
            int r = i & 127, cq = i >> 7;
            float4 v = src[(size_t)r * 32 + cq];
            float* d = As + (cq * 4) * 128 + r;
            d[0] = v.x; d[128] = v.y; d[256] = v.z; d[384] = v.w;
        }
        const float4* srcb = (const float4*)W;
        #pragma unroll
        for (int i = tid; i < 128 * 32; i += 256) {
            int r = i & 127, cq = i >> 7;
            float4 v = srcb[(size_t)r * 32 + cq];
            float* d = Bs + (cq * 4) * 128 + r;
            d[0] = v.x; d[128] = v.y; d[256] = v.z; d[384] = v.w;
        }
    }
    __syncthreads();

    float acc[8][8];
    #pragma unroll
    for (int i = 0; i < 8; i++)
        #pragma unroll
        for (int j = 0; j < 8; j++) acc[i][j] = 0.f;

    #pragma unroll 4
    for (int c = 0; c < 128; c++) {
        const float* ac = As + c * 128;
        const float* bc = Bs + c * 128;
        float4 a0 = *(const float4*)(ac + ty * 4);
        float4 a1 = *(const float4*)(ac + 64 + ty * 4);
        float4 b0 = *(const float4*)(bc + tx * 4);
        float4 b1 = *(const float4*)(bc + 64 + tx * 4);
        float a[8] = {a0.x, a0.y, a0.z, a0.w, a1.x, a1.y, a1.z, a1.w};
        float b[8] = {b0.x, b0.y, b0.z, b0.w, b1.x, b1.y, b1.z, b1.w};
        #pragma unroll
        for (int i = 0; i < 8; i++)
            #pragma unroll
            for (int j = 0; j < 8; j++)
                acc[i][j] += a[i] * b[j];
    }

    #pragma unroll
    for (int ih = 0; ih < 2; ih++) {
        #pragma unroll
        for (int i = 0; i < 4; i++) {
            const int row = m0 + ih * 64 + ty * 4 + i;
            #pragma unroll
            for (int jh = 0; jh < 2; jh++) {
                const int col = jh * 64 + tx * 4;
                float a0 = acc[ih * 4 + i][jh * 4 + 0];
                float a1 = acc[ih * 4 + i][jh * 4 + 1];
                float a2 = acc[ih * 4 + i][jh * 4 + 2];
                float a3 = acc[ih * 4 + i][jh * 4 + 3];
                *(float4*)(df + (size_t)row * 128 + col) = make_float4(a0, a1, a2, a3);
                __nv_bfloat162 p01, p23;
                p01.x = __float2bfloat16_rn(a0 * bscale);
                p01.y = __float2bfloat16_rn(a1 * bscale);
                p23.x = __float2bfloat16_rn(a2 * bscale);
                p23.y = __float2bfloat16_rn(a3 * bscale);
                __nv_bfloat162* pb = (__nv_bfloat162*)(db + (size_t)row * 128 + col);
                pb[0] = p01; pb[1] = p23;
            }
        }
    }
}

// ============================================================================
// Approx scores via mma.sync bf16: S[n][q][k] (Q pre-scaled). CTA = 128q x 128k.
// 8 warps, warp = 16 q rows. A-frags in regs (ldmatrix.x4), B via LDS.32
// from 272B-padded K rows (bank = 4g+c -> conflict-free).
// ============================================================================
__global__ __launch_bounds__(256) void scores_mma()
{
    extern __shared__ __align__(16) char smc[];
    const int tid = threadIdx.x, lane = tid & 31, w = tid >> 5;
    const int n = blockIdx.z, m0 = blockIdx.y * 128, k0 = blockIdx.x * 128;
    const int KOFF = 128 * 272;  // 34816

    // load tiles into padded smem (row stride 272 B)
    {
        const uint4* gq = (const uint4*)(g_Qb + ((size_t)n * TSEQ + m0) * CDIM);
        const uint4* gk = (const uint4*)(g_Kb + ((size_t)n * TSEQ + k0) * CDIM);
        #pragma unroll
        for (int j = 0; j < 8; j++) {
            int i = tid + j * 256;
            int r = i >> 4, cq = i & 15;
            *(uint4*)(smc + r * 272 + cq * 16) = gq[i];
            *(uint4*)(smc + KOFF + r * 272 + cq * 16) = gk[i];
        }
    }
    __syncthreads();

    const uint32_t sbase = s2u(smc);
    const int g = lane >> 2, c4 = lane & 3;

    // A fragments: 8 k-steps x 4 regs (persist)
    uint32_t A[8][4];
    {
        uint32_t qaddr = sbase + (uint32_t)(w * 16 + (lane & 15)) * 272 + (uint32_t)((lane >> 4) * 16);
        #pragma unroll
        for (int ks = 0; ks < 8; ks++) {
            asm volatile("ldmatrix.sync.aligned.m8n8.x4.shared.b16 {%0,%1,%2,%3}, [%4];"
                : "=r"(A[ks][0]), "=r"(A[ks][1]), "=r"(A[ks][2]), "=r"(A[ks][3])
                : "r"(qaddr + ks * 32));
        }
    }

    float* Sout = g_S + ((size_t)n * TSEQ + m0 + w * 16) * TSEQ + k0;

    #pragma unroll
    for (int nt = 0; nt < 16; nt++) {
        float c0 = 0.f, c1 = 0.f, c2 = 0.f, c3 = 0.f;
        const char* brow = smc + KOFF + (nt * 8 + g) * 272 + c4 * 4;
        #pragma unroll
        for (int ks = 0; ks < 8; ks++) {
            uint32_t b0 = *(const uint32_t*)(brow + ks * 32);
            uint32_t b1 = *(const uint32_t*)(brow + ks * 32 + 16);
            asm volatile(
                "mma.sync.aligned.m16n8k16.row.col.f32.bf16.bf16.f32 "
                "{%0,%1,%2,%3}, {%4,%5,%6,%7}, {%8,%9}, {%0,%1,%2,%3};"
                : "+f"(c0), "+f"(c1), "+f"(c2), "+f"(c3)
                : "r"(A[ks][0]), "r"(A[ks][1]), "r"(A[ks][2]), "r"(A[ks][3]),
                  "r"(b0), "r"(b1));
        }
        const int col = nt * 8 + 2 * c4;
        *(float2*)(Sout + (size_t)g * TSEQ + col)       = make_float2(c0, c1);
        *(float2*)(Sout + (size_t)(g + 8) * TSEQ + col) = make_float2(c2, c3);
    }
}

// ============================================================================
// Fused: per (n,q) row (one warp): candidate top-6 from approx S (packed uint
// chains), exact fp32 rescore of 6, top-3 + softmax, sparse attention row
// write, and A@V gather.
// ============================================================================
#define PMAP(f, u) { uint32_t _b = __float_as_uint(f); (u) = ((int)_b < 0) ? ~_b : (_b | 0x80000000u); }
#define CH4(x) { uint32_t _x = (x), _t; _t = umin(v0, _x); v0 = umax(v0, _x); \
                 _x = _t; _t = umin(v1, _x); v1 = umax(v1, _x);              \
                 _x = _t; _t = umin(v2, _x); v2 = umax(v2, _x);              \
                 v3 = umax(v3, _t); }
#define INS6(x) { uint32_t _x = (x), _t; _t = umin(u0, _x); u0 = umax(u0, _x); \
                  _x = _t; _t = umin(u1, _x); u1 = umax(u1, _x);              \
                  _x = _t; _t = umin(u2, _x); u2 = umax(u2, _x);              \
                  _x = _t; _t = umin(u3, _x); u3 = umax(u3, _x);              \
                  _x = _t; _t = umin(u4, _x); u4 = umax(u4, _x);              \
                  u5 = umax(u5, _t); }
#define INS(vv, cc) do { float _v = (vv); int _c = (cc);                     \
    if (_v > b2) {                                                           \
        if (_v > b1) {                                                       \
            if (_v > b0) { b2 = b1; i2 = i1; b1 = b0; i1 = i0; b0 = _v; i0 = _c; } \
            else         { b2 = b1; i2 = i1; b1 = _v; i1 = _c; }             \
        } else           { b2 = _v; i2 = _c; }                               \
    } } while (0)

__global__ __launch_bounds__(256) void topk_fused(
    const float* __restrict__ E, float* __restrict__ attn)
{
    const int gw   = (blockIdx.x * 256 + threadIdx.x) >> 5;  // n*2048+q
    const int lane = threadIdx.x & 31;
    const int n = gw >> 11;

    const float4* r4 = (const float4*)(g_S + (size_t)gw * TSEQ);

    uint32_t v0 = 0, v1 = 0, v2 = 0, v3 = 0;
    #pragma unroll
    for (int f = 0; f < 16; f++) {
        float4 x = r4[f * 32 + lane];
        uint32_t c = (uint32_t)(f * 128 + lane * 4), m;
        PMAP(x.x, m); CH4((m & 0xFFFFF800u) | c);
        PMAP(x.y, m); CH4((m & 0xFFFFF800u) | (c + 1));
        PMAP(x.z, m); CH4((m & 0xFFFFF800u) | (c + 2));
        PMAP(x.w, m); CH4((m & 0xFFFFF800u) | (c + 3));
    }

    uint32_t u0 = v0, u1 = v1, u2 = v2, u3 = v3, u4 = 0, u5 = 0;
    #pragma unroll
    for (int off = 16; off; off >>= 1) {
        uint32_t w0 = __shfl_down_sync(0xffffffffu, u0, off);
        uint32_t w1 = __shfl_down_sync(0xffffffffu, u1, off);
        uint32_t w2 = __shfl_down_sync(0xffffffffu, u2, off);
        uint32_t w3 = __shfl_down_sync(0xffffffffu, u3, off);
        uint32_t w4 = __shfl_down_sync(0xffffffffu, u4, off);
        uint32_t w5 = __shfl_down_sync(0xffffffffu, u5, off);
        INS6(w0); INS6(w1); INS6(w2); INS6(w3); INS6(w4); INS6(w5);
    }
    u0 = __shfl_sync(0xffffffffu, u0, 0);
    u1 = __shfl_sync(0xffffffffu, u1, 0);
    u2 = __shfl_sync(0xffffffffu, u2, 0);
    u3 = __shfl_sync(0xffffffffu, u3, 0);
    u4 = __shfl_sync(0xffffffffu, u4, 0);
    u5 = __shfl_sync(0xffffffffu, u5, 0);

    int id[6] = { (int)(u0 & 2047u), (int)(u1 & 2047u), (int)(u2 & 2047u),
                  (int)(u3 & 2047u), (int)(u4 & 2047u), (int)(u5 & 2047u) };

    // ---- exact fp32 rescore of the 6 candidates ----
    float4 qv = ((const float4*)(g_Qf + (size_t)gw * CDIM))[lane];
    float4 kv[6];
    #pragma unroll
    for (int j = 0; j < 6; j++)
        kv[j] = ((const float4*)(g_Kf + ((size_t)(n * TSEQ + id[j])) * CDIM))[lane];
    float s[6];
    #pragma unroll
    for (int j = 0; j < 6; j++)
        s[j] = qv.x * kv[j].x + qv.y * kv[j].y + qv.z * kv[j].z + qv.w * kv[j].w;
    #pragma unroll
    for (int off = 16; off; off >>= 1)
        #pragma unroll
        for (int j = 0; j < 6; j++)
            s[j] += __shfl_xor_sync(0xffffffffu, s[j], off);

    float b0 = -INFINITY, b1 = -INFINITY, b2 = -INFINITY;
    int i0 = 0, i1 = 0, i2 = 0;
    #pragma unroll
    for (int j = 0; j < 6; j++) INS(s[j] * SCL, id[j]);

    const float e1 = expf(b1 - b0);
    const float e2 = expf(b2 - b0);
    const float inv = 1.f / (1.f + e1 + e2);
    const float w0 = inv, w1 = e1 * inv, w2 = e2 * inv;

    // ---- write sparse attention row ----
    float4* a4 = (float4*)(attn + (size_t)gw * TSEQ);
    #pragma unroll
    for (int f = 0; f < 16; f++) {
        const int c = f * 128 + lane * 4;
        float4 z;
        z.x = (i0 == c    ) ? w0 : (i1 == c    ) ? w1 : (i2 == c    ) ? w2 : 0.f;
        z.y = (i0 == c + 1) ? w0 : (i1 == c + 1) ? w1 : (i2 == c + 1) ? w2 : 0.f;
        z.z = (i0 == c + 2) ? w0 : (i1 == c + 2) ? w1 : (i2 == c + 2) ? w2 : 0.f;
        z.w = (i0 == c + 3) ? w0 : (i1 == c + 3) ? w1 : (i2 == c + 3) ? w2 : 0.f;
        a4[f * 32 + lane] = z;
    }

    // ---- A @ V gather (V = raw embeddings) ----
    const float4* V0 = (const float4*)(E + ((size_t)(n * TSEQ + i0)) * CDIM);
    const float4* V1 = (const float4*)(E + ((size_t)(n * TSEQ + i1)) * CDIM);
    const float4* V2 = (const float4*)(E + ((size_t)(n * TSEQ + i2)) * CDIM);
    float4 p0 = V0[lane], p1 = V1[lane], p2 = V2[lane];
    float4 o;
    o.x = w0 * p0.x + w1 * p1.x + w2 * p2.x;
    o.y = w0 * p0.y + w1 * p1.y + w2 * p2.y;
    o.z = w0 * p0.z + w1 * p1.z + w2 * p2.z;
    o.w = w0 * p0.w + w1 * p1.w + w2 * p2.w;
    *(float4*)(g_OA + (size_t)gw * CDIM + lane * 4) = o;
}

// ============================================================================
// Output projection: out = OA @ Wo^T + bo (SIMT fp32)
// ============================================================================
__global__ __launch_bounds__(256) void gemm_out(
    const float* __restrict__ B, const float* __restrict__ bias, float* __restrict__ Cc)
{
    extern __shared__ float smf[];
    float* As = smf;
    float* Bs = smf + 128 * 128;
    const int tid = threadIdx.x, tx = tid & 15, ty = tid >> 4;
    const int m0 = blockIdx.x * 128;

    {
        const float4* src = (const float4*)(g_OA + (size_t)m0 * 128);
        #pragma unroll
        for (int i = tid; i < 128 * 32; i += 256) {
            int r = i & 127, cq = i >> 7;
            float4 v = src[(size_t)r * 32 + cq];
            float* d = As + (cq * 4) * 128 + r;
            d[0] = v.x; d[128] = v.y; d[256] = v.z; d[384] = v.w;
        }
        const float4* srcb = (const float4*)B;
        #pragma unroll
        for (int i = tid; i < 128 * 32; i += 256) {
            int r = i & 127, cq = i >> 7;
            float4 v = srcb[(size_t)r * 32 + cq];
            float* d = Bs + (cq * 4) * 128 + r;
            d[0] = v.x; d[128] = v.y; d[256] = v.z; d[384] = v.w;
        }
    }
    __syncthreads();

    float acc[8][8];
    #pragma unroll
    for (int i = 0; i < 8; i++)
        #pragma unroll
        for (int j = 0; j < 8; j++) acc[i][j] = 0.f;

    #pragma unroll 4
    for (int c = 0; c < 128; c++) {
        const float* ac = As + c * 128;
        const float* bc = Bs + c * 128;
        float4 a0 = *(const float4*)(ac + ty * 4);
        float4 a1 = *(const float4*)(ac + 64 + ty * 4);
        float4 b0 = *(const float4*)(bc + tx * 4);
        float4 b1 = *(const float4*)(bc + 64 + tx * 4);
        float a[8] = {a0.x, a0.y, a0.z, a0.w, a1.x, a1.y, a1.z, a1.w};
        float b[8] = {b0.x, b0.y, b0.z, b0.w, b1.x, b1.y, b1.z, b1.w};
        #pragma unroll
        for (int i = 0; i < 8; i++)
            #pragma unroll
            for (int j = 0; j < 8; j++)
                acc[i][j] += a[i] * b[j];
    }

    #pragma unroll
    for (int ih = 0; ih < 2; ih++) {
        #pragma unroll
        for (int i = 0; i < 4; i++) {
            const int row = m0 + ih * 64 + ty * 4 + i;
            #pragma unroll
            for (int jh = 0; jh < 2; jh++) {
                const int col = jh * 64 + tx * 4;
                float4 bb = *(const float4*)(bias + col);
                float4 o;
                o.x = acc[ih * 4 + i][jh * 4 + 0] + bb.x;
                o.y = acc[ih * 4 + i][jh * 4 + 1] + bb.y;
                o.z = acc[ih * 4 + i][jh * 4 + 2] + bb.z;
                o.w = acc[ih * 4 + i][jh * 4 + 3] + bb.w;
                *(float4*)(Cc + (size_t)row * 128 + col) = o;
            }
        }
    }
}

// ============================================================================
extern "C" void kernel_launch(void* const* d_in, const int* in_sizes, int n_in,
                              void* d_out, int out_size)
{
    const float* E  = (const float*)d_in[0];
    const float* Wq = (const float*)d_in[2];
    const float* Wk = (const float*)d_in[3];
    const float* Wo = (const float*)d_in[4];
    const float* bo = (const float*)d_in[5];

    float* out  = (float*)d_out;                       // [8,2048,128]
    float* attn = out + (size_t)NBATCH * TSEQ * CDIM;  // [8,1,2048,2048]

    const int SMEM_G = 128 * 128 * 2 * sizeof(float);  // 131072
    const int SMEM_S = 2 * 128 * 272;                  // 69632
    cudaFuncSetAttribute(proj_split, cudaFuncAttributeMaxDynamicSharedMemorySize, SMEM_G);
    cudaFuncSetAttribute(gemm_out,   cudaFuncAttributeMaxDynamicSharedMemorySize, SMEM_G);
    cudaFuncSetAttribute(scores_mma, cudaFuncAttributeMaxDynamicSharedMemorySize, SMEM_S);

    // Q/K projections -> fp32 + bf16 (Q pre-scaled)
    proj_split<<<dim3(128, 2), 256, SMEM_G>>>(E, Wq, Wk);

    // approx scores via bf16 HMMA
    scores_mma<<<dim3(16, 16, NBATCH), 256, SMEM_S>>>();

    // candidates + exact rescore + softmax + attention write + A@V
    topk_fused<<<2048, 256>>>(E, attn);

    // out = OA @ Wo^T + bo
    gemm_out<<<128, 256, SMEM_G>>>(Wo, bo, out);
}